// round 1
// baseline (speedup 1.0000x reference)
#include <cuda_runtime.h>
#include <math.h>

// Problem constants
#define B_SZ    2
#define N_NODES 4096
#define F_INC   256
#define F_OUTC  64
#define TI      16     // rows per attention block
#define TJ      128    // j-tile
#define NCHUNK  (N_NODES / TJ)          // 32
#define NBLK_I  (N_NODES / TI)          // 256 per batch
#define TOT_BLK (B_SZ * NBLK_I)         // 512
#define EPSV    1e-5f
#define SLOPE   0.01f

// ---------- device scratch (no allocations allowed) ----------
__device__ float g_fts[B_SZ * N_NODES * F_OUTC];
__device__ float g_f1[B_SZ * N_NODES];
__device__ float g_f2[B_SZ * N_NODES];
__device__ float g_vals[B_SZ * N_NODES * F_OUTC];
__device__ float g_p1[TOT_BLK * F_OUTC];
__device__ float g_p2[TOT_BLK * F_OUTC];
__device__ float g_ab[2 * F_OUTC];

// ============================================================
// Kernel 1: seq_fts = seq @ W1^T ; f1 = fts.w2 + b2 ; f2 = fts.w3 + b3
// grid: 512 blocks x 256 threads, 16 rows per block
// ============================================================
__global__ void k_proj(const float* __restrict__ seq,
                       const float* __restrict__ W1,
                       const float* __restrict__ w2,
                       const float* __restrict__ b2,
                       const float* __restrict__ w3,
                       const float* __restrict__ b3) {
    __shared__ __align__(16) float s_seq[16][F_INC];
    __shared__ float s_fts[16][F_OUTC + 4];

    const int t = threadIdx.x;                  // 256 threads
    const int rg0 = blockIdx.x * 16;            // global row base (0..8191)

    // load 16 rows of seq (16*256 floats) via float4
    {
        const float4* src = (const float4*)(seq + (size_t)rg0 * F_INC);
        float4* dst = (float4*)&s_seq[0][0];
        #pragma unroll
        for (int i = 0; i < (16 * F_INC / 4) / 256; i++)
            dst[t + i * 256] = src[t + i * 256];
    }
    __syncthreads();

    const int r  = t >> 4;          // 0..15
    const int c0 = (t & 15) * 4;    // 0..60
    float a0 = 0.f, a1 = 0.f, a2 = 0.f, a3 = 0.f;
    const float* wp = W1 + (size_t)c0 * F_INC;
    #pragma unroll 4
    for (int k = 0; k < F_INC; k += 4) {
        float4 sv  = *(const float4*)&s_seq[r][k];
        float4 w0v = __ldg((const float4*)(wp + k));
        float4 w1v = __ldg((const float4*)(wp + F_INC + k));
        float4 w2v = __ldg((const float4*)(wp + 2 * F_INC + k));
        float4 w3v = __ldg((const float4*)(wp + 3 * F_INC + k));
        a0 += sv.x * w0v.x + sv.y * w0v.y + sv.z * w0v.z + sv.w * w0v.w;
        a1 += sv.x * w1v.x + sv.y * w1v.y + sv.z * w1v.z + sv.w * w1v.w;
        a2 += sv.x * w2v.x + sv.y * w2v.y + sv.z * w2v.z + sv.w * w2v.w;
        a3 += sv.x * w3v.x + sv.y * w3v.y + sv.z * w3v.z + sv.w * w3v.w;
    }
    s_fts[r][c0 + 0] = a0;
    s_fts[r][c0 + 1] = a1;
    s_fts[r][c0 + 2] = a2;
    s_fts[r][c0 + 3] = a3;
    {
        float4 st; st.x = a0; st.y = a1; st.z = a2; st.w = a3;
        *(float4*)(g_fts + ((size_t)(rg0 + r)) * F_OUTC + c0) = st;
    }
    __syncthreads();

    if (t < 32) {
        int row = t >> 1;
        int sel = t & 1;
        const float* wv = sel ? w3 : w2;
        float acc = sel ? b3[0] : b2[0];
        #pragma unroll 8
        for (int c = 0; c < F_OUTC; c++) acc += s_fts[row][c] * wv[c];
        if (sel) g_f2[rg0 + row] = acc;
        else     g_f1[rg0 + row] = acc;
    }
}

// ============================================================
// Kernel 2: flash-style attention + per-block BN partial sums
// grid: (256, 2) x 256 threads. Block handles TI=16 rows, streams all j.
// Warp layout (FMA phase): warp = half*4 + wq; half splits j-range [0,64)/[64,128);
//   lane: rl = lane>>3 (row within quad), cl = lane&7 (8 channels = 2 float4)
// ============================================================
__global__ void k_attn(const float* __restrict__ bias) {
    __shared__ __align__(16) float s_fts[TJ * F_OUTC];   // 32KB, reused as vals buf
    __shared__ float s_s[TI][TJ + 2];                    // score / weight buffer
    __shared__ float s_f2[TJ];
    __shared__ float s_f1[TI];
    __shared__ float s_m[TI], s_l[TI], s_scale[TI], s_cmax[TI];

    const int t    = threadIdx.x;
    const int warp = t >> 5;
    const int lane = t & 31;
    const int b    = blockIdx.y;
    const int i0   = blockIdx.x * TI;

    if (t < TI) {
        s_f1[t] = g_f1[b * N_NODES + i0 + t];
        s_m[t]  = -1e30f;
        s_l[t]  = 0.f;
    }

    const int wq    = warp & 3;
    const int half  = warp >> 2;
    const int rl    = lane >> 3;
    const int cl    = lane & 7;
    const int i_loc = wq * 4 + rl;
    const int jbase = half * 64;

    float acc[8];
    #pragma unroll
    for (int k = 0; k < 8; k++) acc[k] = 0.f;

    const float* ftsb  = g_fts + (size_t)b * N_NODES * F_OUTC;
    const float* biasb = bias + ((size_t)b * N_NODES + i0) * N_NODES;

    __syncthreads();

    for (int chk = 0; chk < NCHUNK; chk++) {
        const int j0 = chk * TJ;

        // ---- load fts tile (TJ x 64) + f2 chunk ----
        {
            const float4* src = (const float4*)(ftsb + (size_t)j0 * F_OUTC);
            float4* dst = (float4*)s_fts;
            #pragma unroll
            for (int i = 0; i < (TJ * F_OUTC / 4) / 256; i++)
                dst[t + i * 256] = src[t + i * 256];
            if (t < TJ) s_f2[t] = g_f2[b * N_NODES + j0 + t];
        }
        __syncthreads();

        // ---- score phase: s = lrelu(f1+f2)+bias ; per-row chunk max ----
        #pragma unroll
        for (int p = 0; p < 2; p++) {
            const int row = warp * 2 + p;
            const float f1v = s_f1[row];
            float mx = -1e30f;
            const float* brow = biasb + (size_t)row * N_NODES + j0;
            #pragma unroll
            for (int k = 0; k < 4; k++) {
                int j = lane + 32 * k;
                float x = f1v + s_f2[j];
                x = x > 0.f ? x : SLOPE * x;
                x += __ldg(brow + j);
                s_s[row][j] = x;
                mx = fmaxf(mx, x);
            }
            #pragma unroll
            for (int o = 16; o; o >>= 1)
                mx = fmaxf(mx, __shfl_xor_sync(0xffffffffu, mx, o));
            if (lane == 0) s_cmax[row] = mx;
        }
        __syncthreads();

        // ---- online-softmax state update ----
        if (t < TI) {
            float mo = s_m[t];
            float mn = fmaxf(mo, s_cmax[t]);
            float sc = __expf(mo - mn);
            s_m[t] = mn;
            s_scale[t] = sc;
            s_l[t] *= sc;
        }
        __syncthreads();

        {
            const float sc = s_scale[i_loc];
            #pragma unroll
            for (int k = 0; k < 8; k++) acc[k] *= sc;
        }

        // ---- exp phase: w = exp(s - m); row sums ----
        #pragma unroll
        for (int p = 0; p < 2; p++) {
            const int row = warp * 2 + p;
            const float mrow = s_m[row];
            float ls = 0.f;
            #pragma unroll
            for (int k = 0; k < 4; k++) {
                int j = lane + 32 * k;
                float w = __expf(s_s[row][j] - mrow);
                s_s[row][j] = w;
                ls += w;
            }
            #pragma unroll
            for (int o = 16; o; o >>= 1)
                ls += __shfl_xor_sync(0xffffffffu, ls, o);
            if (lane == 0) s_l[row] += ls;
        }
        __syncthreads();

        // ---- FMA accumulation: acc += w[j] * fts[j][ch] ----
        #pragma unroll 4
        for (int j = 0; j < 64; j++) {
            const float w = s_s[i_loc][jbase + j];
            const float* fr = s_fts + (jbase + j) * F_OUTC;
            float4 fa = *(const float4*)(fr + cl * 4);
            float4 fb = *(const float4*)(fr + 32 + cl * 4);
            acc[0] += w * fa.x; acc[1] += w * fa.y;
            acc[2] += w * fa.z; acc[3] += w * fa.w;
            acc[4] += w * fb.x; acc[5] += w * fb.y;
            acc[6] += w * fb.z; acc[7] += w * fb.w;
        }
        __syncthreads();
    }

    // ---- combine the two j-halves, normalize, write vals ----
    float* buf = s_fts;   // reuse as [TI][64]
    const float inv_l = 1.f / s_l[i_loc];

    if (half == 0) {
        float4 va; va.x = acc[0]; va.y = acc[1]; va.z = acc[2]; va.w = acc[3];
        float4 vb; vb.x = acc[4]; vb.y = acc[5]; vb.z = acc[6]; vb.w = acc[7];
        *(float4*)(buf + i_loc * F_OUTC + cl * 4) = va;
        *(float4*)(buf + i_loc * F_OUTC + 32 + cl * 4) = vb;
    }
    __syncthreads();
    if (half == 1) {
        float* pa = buf + i_loc * F_OUTC + cl * 4;
        float* pb = pa + 32;
        pa[0] += acc[0]; pa[1] += acc[1]; pa[2] += acc[2]; pa[3] += acc[3];
        pb[0] += acc[4]; pb[1] += acc[5]; pb[2] += acc[6]; pb[3] += acc[7];
    }
    __syncthreads();
    if (half == 0) {
        float* pa = buf + i_loc * F_OUTC + cl * 4;
        float* pb = pa + 32;
        float4 va, vb;
        va.x = pa[0] * inv_l; va.y = pa[1] * inv_l;
        va.z = pa[2] * inv_l; va.w = pa[3] * inv_l;
        vb.x = pb[0] * inv_l; vb.y = pb[1] * inv_l;
        vb.z = pb[2] * inv_l; vb.w = pb[3] * inv_l;
        *(float4*)pa = va;
        *(float4*)pb = vb;
        float* go = g_vals + ((size_t)b * N_NODES + i0 + i_loc) * F_OUTC;
        *(float4*)(go + cl * 4) = va;
        *(float4*)(go + 32 + cl * 4) = vb;
    }
    __syncthreads();

    // ---- deterministic per-block BN partials ----
    if (t < F_OUTC) {
        float s1 = 0.f, s2 = 0.f;
        #pragma unroll
        for (int r = 0; r < TI; r++) {
            float v = buf[r * F_OUTC + t];
            s1 += v;
            s2 += v * v;
        }
        const int bid = b * gridDim.x + blockIdx.x;
        g_p1[bid * F_OUTC + t] = s1;
        g_p2[bid * F_OUTC + t] = s2;
    }
}

// ============================================================
// Kernel 3: reduce BN partials -> per-channel scale/shift
// ============================================================
__global__ void k_stats(const float* __restrict__ gamma,
                        const float* __restrict__ beta) {
    const int c = threadIdx.x;   // 64 threads
    float s1 = 0.f, s2 = 0.f;
    for (int i = 0; i < TOT_BLK; i++) {
        s1 += g_p1[i * F_OUTC + c];
        s2 += g_p2[i * F_OUTC + c];
    }
    const float inv_n = 1.f / (float)(B_SZ * N_NODES);
    const float mean = s1 * inv_n;
    const float var  = s2 * inv_n - mean * mean;
    const float a = gamma[c] * rsqrtf(var + EPSV);
    g_ab[c]          = a;
    g_ab[F_OUTC + c] = beta[c] - mean * a;
}

// ============================================================
// Kernel 4: apply BN + ELU
// ============================================================
__global__ void k_bn_elu(float* __restrict__ out) {
    __shared__ float sa[F_OUTC], sb[F_OUTC];
    if (threadIdx.x < F_OUTC) {
        sa[threadIdx.x] = g_ab[threadIdx.x];
        sb[threadIdx.x] = g_ab[F_OUTC + threadIdx.x];
    }
    __syncthreads();
    const int idx = blockIdx.x * blockDim.x + threadIdx.x;
    const int c = idx & (F_OUTC - 1);
    float v = g_vals[idx] * sa[c] + sb[c];
    out[idx] = v > 0.f ? v : expm1f(v);
}

// ============================================================
// launch
// ============================================================
extern "C" void kernel_launch(void* const* d_in, const int* in_sizes, int n_in,
                              void* d_out, int out_size) {
    const float* seq      = (const float*)d_in[0];   // [2,4096,256]
    const float* bias_mat = (const float*)d_in[1];   // [2,4096,4096]
    const float* W1       = (const float*)d_in[2];   // [64,256]
    const float* w2       = (const float*)d_in[3];   // [64]
    const float* b2       = (const float*)d_in[4];   // [1]
    const float* w3       = (const float*)d_in[5];   // [64]
    const float* b3       = (const float*)d_in[6];   // [1]
    const float* gamma    = (const float*)d_in[7];   // [64]
    const float* beta     = (const float*)d_in[8];   // [64]
    float* out = (float*)d_out;                      // [2,4096,64]

    k_proj<<<B_SZ * N_NODES / 16, 256>>>(seq, W1, w2, b2, w3, b3);
    k_attn<<<dim3(NBLK_I, B_SZ), 256>>>(bias_mat);
    k_stats<<<1, F_OUTC>>>(gamma, beta);
    k_bn_elu<<<(B_SZ * N_NODES * F_OUTC) / 256, 256>>>(out);
}

// round 3
// speedup vs baseline: 1.5292x; 1.5292x over previous
#include <cuda_runtime.h>
#include <cuda_fp16.h>
#include <math.h>
#include <stdint.h>

// ---------------- problem constants ----------------
#define B_SZ    2
#define N_NODES 4096
#define F_INC   256
#define F_OUTC  64
#define TI      64               // i-rows per attention CTA
#define TJ      128              // j-chunk
#define NCHUNK  (N_NODES / TJ)   // 32
#define NBLK    (N_NODES / TI)   // 64 per batch
#define TOT_BLK (B_SZ * NBLK)    // 128
#define EPSV    1e-5f
#define SLOPE   0.01f

// ---------------- device scratch ----------------
__device__ __half g_fts_h[B_SZ * N_NODES * F_OUTC];
__device__ float  g_f1[B_SZ * N_NODES];
__device__ float  g_f2[B_SZ * N_NODES];
__device__ float  g_f2max[B_SZ];
__device__ float  g_vals[B_SZ * N_NODES * F_OUTC];
__device__ float  g_p1[TOT_BLK * F_OUTC];
__device__ float  g_p2[TOT_BLK * F_OUTC];
__device__ float  g_ab[2 * F_OUTC];

// ---------------- mma / ldmatrix helpers (baseline PTX, sm_80+) ----------------
__device__ __forceinline__ void mma16816(float* c, const uint32_t* a, const uint32_t* b) {
    asm volatile("mma.sync.aligned.m16n8k16.row.col.f32.f16.f16.f32 "
        "{%0,%1,%2,%3}, {%4,%5,%6,%7}, {%8,%9}, {%0,%1,%2,%3};"
        : "+f"(c[0]), "+f"(c[1]), "+f"(c[2]), "+f"(c[3])
        : "r"(a[0]), "r"(a[1]), "r"(a[2]), "r"(a[3]), "r"(b[0]), "r"(b[1]));
}
__device__ __forceinline__ void ldsm4t(uint32_t* r, uint32_t addr) {
    asm volatile("ldmatrix.sync.aligned.m8n8.x4.trans.shared.b16 {%0,%1,%2,%3}, [%4];"
        : "=r"(r[0]), "=r"(r[1]), "=r"(r[2]), "=r"(r[3]) : "r"(addr));
}
__device__ __forceinline__ uint32_t smem_u32(const void* p) {
    return (uint32_t)__cvta_generic_to_shared(p);
}
__device__ __forceinline__ float lrelu(float x) {
    return x > 0.f ? x : SLOPE * x;
}

// ============================================================
// Kernel 1: projection + f1/f2 + fp16 fts
// ============================================================
__global__ void k_proj(const float* __restrict__ seq,
                       const float* __restrict__ W1,
                       const float* __restrict__ w2,
                       const float* __restrict__ b2,
                       const float* __restrict__ w3,
                       const float* __restrict__ b3) {
    __shared__ __align__(16) float s_seq[16][F_INC];
    __shared__ float s_fts[16][F_OUTC + 4];

    const int t = threadIdx.x;
    const int rg0 = blockIdx.x * 16;

    {
        const float4* src = (const float4*)(seq + (size_t)rg0 * F_INC);
        float4* dst = (float4*)&s_seq[0][0];
        #pragma unroll
        for (int i = 0; i < (16 * F_INC / 4) / 256; i++)
            dst[t + i * 256] = src[t + i * 256];
    }
    __syncthreads();

    const int r  = t >> 4;
    const int c0 = (t & 15) * 4;
    float a0 = 0.f, a1 = 0.f, a2 = 0.f, a3 = 0.f;
    const float* wp = W1 + (size_t)c0 * F_INC;
    #pragma unroll 4
    for (int k = 0; k < F_INC; k += 4) {
        float4 sv  = *(const float4*)&s_seq[r][k];
        float4 w0v = __ldg((const float4*)(wp + k));
        float4 w1v = __ldg((const float4*)(wp + F_INC + k));
        float4 w2v = __ldg((const float4*)(wp + 2 * F_INC + k));
        float4 w3v = __ldg((const float4*)(wp + 3 * F_INC + k));
        a0 += sv.x * w0v.x + sv.y * w0v.y + sv.z * w0v.z + sv.w * w0v.w;
        a1 += sv.x * w1v.x + sv.y * w1v.y + sv.z * w1v.z + sv.w * w1v.w;
        a2 += sv.x * w2v.x + sv.y * w2v.y + sv.z * w2v.z + sv.w * w2v.w;
        a3 += sv.x * w3v.x + sv.y * w3v.y + sv.z * w3v.z + sv.w * w3v.w;
    }
    s_fts[r][c0 + 0] = a0;
    s_fts[r][c0 + 1] = a1;
    s_fts[r][c0 + 2] = a2;
    s_fts[r][c0 + 3] = a3;
    {
        __half2 h01 = __floats2half2_rn(a0, a1);
        __half2 h23 = __floats2half2_rn(a2, a3);
        uint2 u;
        u.x = *reinterpret_cast<uint32_t*>(&h01);
        u.y = *reinterpret_cast<uint32_t*>(&h23);
        *(uint2*)(g_fts_h + ((size_t)(rg0 + r)) * F_OUTC + c0) = u;
    }
    __syncthreads();

    if (t < 32) {
        int row = t >> 1;
        int sel = t & 1;
        const float* wv = sel ? w3 : w2;
        float acc = sel ? b3[0] : b2[0];
        #pragma unroll 8
        for (int c = 0; c < F_OUTC; c++) acc += s_fts[row][c] * wv[c];
        if (sel) g_f2[rg0 + row] = acc;
        else     g_f1[rg0 + row] = acc;
    }
}

// ============================================================
// Kernel 1b: per-batch max of f2
// ============================================================
__global__ void k_f2max() {
    __shared__ float red[256];
    const int b = blockIdx.x, t = threadIdx.x;
    float m = -1e30f;
    for (int i = t; i < N_NODES; i += 256)
        m = fmaxf(m, g_f2[b * N_NODES + i]);
    red[t] = m;
    __syncthreads();
    for (int o = 128; o; o >>= 1) {
        if (t < o) red[t] = fmaxf(red[t], red[t + o]);
        __syncthreads();
    }
    if (t == 0) g_f2max[b] = red[0];
}

// ============================================================
// Kernel 2: HMMA attention. grid (64, 2) x 128 threads (4 warps).
// Warp w owns rows [w*16, w*16+16); lane: g = lane>>2 (rows g, g+8),
// t4 = lane&3 (cols 2t, 2t+1, 2t+8, 2t+9 within each 16-col k-step).
// P computed directly into mma A fragments; V fp16 in swizzled smem.
// ============================================================
__global__ __launch_bounds__(128)
void k_attn(const float* __restrict__ bias) {
    __shared__ __align__(128) __half s_v[TJ * F_OUTC];  // 16 KB, SW128 swizzled
    __shared__ float s_f2[TJ];
    __shared__ float s_bn1[4 * F_OUTC];
    __shared__ float s_bn2[4 * F_OUTC];

    const int t    = threadIdx.x;
    const int warp = t >> 5;
    const int lane = t & 31;
    const int g    = lane >> 2;
    const int t4   = lane & 3;
    const int b    = blockIdx.y;
    const int i0   = blockIdx.x * TI;

    const int row_a = i0 + warp * 16 + g;       // local rows g and g+8
    const int row_b = row_a + 8;

    const float f1a = g_f1[b * N_NODES + row_a];
    const float f1b = g_f1[b * N_NODES + row_b];
    const float f2m = g_f2max[b];
    const float mha = lrelu(f1a + f2m);
    const float mhb = lrelu(f1b + f2m);

    const float* bra = bias + ((size_t)(b * N_NODES + row_a)) * N_NODES;
    const float* brb = bias + ((size_t)(b * N_NODES + row_b)) * N_NODES;

    const uint32_t sv_u32 = smem_u32(s_v);

    float c[8][4];
    #pragma unroll
    for (int nt = 0; nt < 8; nt++)
        #pragma unroll
        for (int k = 0; k < 4; k++) c[nt][k] = 0.f;

    float lsum_a = 0.f, lsum_b = 0.f;

    for (int chk = 0; chk < NCHUNK; ++chk) {
        const int j0 = chk * TJ;
        __syncthreads();   // previous chunk's reads of s_v / s_f2 done

        // load f2 chunk + V tile (swizzled SW128: rows of 128B)
        s_f2[t] = g_f2[b * N_NODES + j0 + t];
        {
            const uint4* vsrc = (const uint4*)(g_fts_h + ((size_t)b * N_NODES + j0) * F_OUTC);
            #pragma unroll
            for (int i = 0; i < 8; ++i) {
                uint32_t idx = (uint32_t)(t + 128 * i);
                uint32_t off = idx * 16u;
                *(uint4*)((char*)s_v + (off ^ ((off >> 3) & 0x70))) = __ldg(vsrc + idx);
            }
        }
        __syncthreads();

        #pragma unroll 2
        for (int kk = 0; kk < 8; ++kk) {
            const int jb = kk * 16 + 2 * t4;   // chunk-local col for this lane

            // ---- A fragments: 8 scores per lane ----
            float2 f20 = *(const float2*)(s_f2 + jb);
            float2 f21 = *(const float2*)(s_f2 + jb + 8);
            float2 ba0 = __ldg((const float2*)(bra + j0 + jb));
            float2 ba1 = __ldg((const float2*)(bra + j0 + jb + 8));
            float2 bb0 = __ldg((const float2*)(brb + j0 + jb));
            float2 bb1 = __ldg((const float2*)(brb + j0 + jb + 8));

            float ea0 = __expf(lrelu(f1a + f20.x) + ba0.x - mha);
            float ea1 = __expf(lrelu(f1a + f20.y) + ba0.y - mha);
            float ea2 = __expf(lrelu(f1a + f21.x) + ba1.x - mha);
            float ea3 = __expf(lrelu(f1a + f21.y) + ba1.y - mha);
            float eb0 = __expf(lrelu(f1b + f20.x) + bb0.x - mhb);
            float eb1 = __expf(lrelu(f1b + f20.y) + bb0.y - mhb);
            float eb2 = __expf(lrelu(f1b + f21.x) + bb1.x - mhb);
            float eb3 = __expf(lrelu(f1b + f21.y) + bb1.y - mhb);

            __half2 ha0 = __floats2half2_rn(ea0, ea1);
            __half2 ha1 = __floats2half2_rn(ea2, ea3);
            __half2 hb0 = __floats2half2_rn(eb0, eb1);
            __half2 hb1 = __floats2half2_rn(eb2, eb3);

            // row sums from the *rounded* halves for consistency
            {
                float2 p;
                p = __half22float2(ha0); lsum_a += p.x + p.y;
                p = __half22float2(ha1); lsum_a += p.x + p.y;
                p = __half22float2(hb0); lsum_b += p.x + p.y;
                p = __half22float2(hb1); lsum_b += p.x + p.y;
            }

            uint32_t a[4];
            a[0] = *reinterpret_cast<uint32_t*>(&ha0);   // (row g,   k 2t,2t+1)
            a[1] = *reinterpret_cast<uint32_t*>(&hb0);   // (row g+8, k 2t,2t+1)
            a[2] = *reinterpret_cast<uint32_t*>(&ha1);   // (row g,   k 2t+8,+9)
            a[3] = *reinterpret_cast<uint32_t*>(&hb1);   // (row g+8, k 2t+8,+9)

            // ---- B fragments: 4 x ldmatrix.x4.trans covering N=64 ----
            const uint32_t krow = (uint32_t)(kk * 16 + (lane & 15));
            #pragma unroll
            for (int nt2 = 0; nt2 < 4; ++nt2) {
                const uint32_t ncol = (uint32_t)((lane >> 4) * 8 + nt2 * 16);
                uint32_t off = krow * 128u + ncol * 2u;
                uint32_t addr = sv_u32 + (off ^ ((off >> 3) & 0x70));
                uint32_t bfr[4];
                ldsm4t(bfr, addr);
                mma16816(c[nt2 * 2 + 0], a, bfr + 0);
                mma16816(c[nt2 * 2 + 1], a, bfr + 2);
            }
        }
    }

    // ---- finalize row sums (butterfly over t4 bits) ----
    lsum_a += __shfl_xor_sync(0xffffffffu, lsum_a, 1);
    lsum_a += __shfl_xor_sync(0xffffffffu, lsum_a, 2);
    lsum_b += __shfl_xor_sync(0xffffffffu, lsum_b, 1);
    lsum_b += __shfl_xor_sync(0xffffffffu, lsum_b, 2);
    const float inv_a = 1.f / lsum_a;
    const float inv_b = 1.f / lsum_b;

    // ---- scale, write vals, accumulate BN partials ----
    float* go_a = g_vals + ((size_t)b * N_NODES + row_a) * F_OUTC;
    float* go_b = g_vals + ((size_t)b * N_NODES + row_b) * F_OUTC;

    #pragma unroll
    for (int nt = 0; nt < 8; ++nt) {
        float2 va, vb;
        va.x = c[nt][0] * inv_a; va.y = c[nt][1] * inv_a;
        vb.x = c[nt][2] * inv_b; vb.y = c[nt][3] * inv_b;
        *(float2*)(go_a + nt * 8 + 2 * t4) = va;
        *(float2*)(go_b + nt * 8 + 2 * t4) = vb;

        float sx = va.x + vb.x, sy = va.y + vb.y;
        float qx = va.x * va.x + vb.x * vb.x;
        float qy = va.y * va.y + vb.y * vb.y;
        #pragma unroll
        for (int o = 4; o < 32; o <<= 1) {
            sx += __shfl_xor_sync(0xffffffffu, sx, o);
            sy += __shfl_xor_sync(0xffffffffu, sy, o);
            qx += __shfl_xor_sync(0xffffffffu, qx, o);
            qy += __shfl_xor_sync(0xffffffffu, qy, o);
        }
        if (g == 0) {
            s_bn1[warp * F_OUTC + nt * 8 + 2 * t4 + 0] = sx;
            s_bn1[warp * F_OUTC + nt * 8 + 2 * t4 + 1] = sy;
            s_bn2[warp * F_OUTC + nt * 8 + 2 * t4 + 0] = qx;
            s_bn2[warp * F_OUTC + nt * 8 + 2 * t4 + 1] = qy;
        }
    }
    __syncthreads();

    if (t < F_OUTC) {
        float s1 = 0.f, s2 = 0.f;
        #pragma unroll
        for (int w = 0; w < 4; ++w) {
            s1 += s_bn1[w * F_OUTC + t];
            s2 += s_bn2[w * F_OUTC + t];
        }
        const int bid = b * NBLK + blockIdx.x;
        g_p1[bid * F_OUTC + t] = s1;
        g_p2[bid * F_OUTC + t] = s2;
    }
}

// ============================================================
// Kernel 3: BN stats
// ============================================================
__global__ void k_stats(const float* __restrict__ gamma,
                        const float* __restrict__ beta) {
    const int c = threadIdx.x;
    float s1 = 0.f, s2 = 0.f;
    for (int i = 0; i < TOT_BLK; i++) {
        s1 += g_p1[i * F_OUTC + c];
        s2 += g_p2[i * F_OUTC + c];
    }
    const float inv_n = 1.f / (float)(B_SZ * N_NODES);
    const float mean = s1 * inv_n;
    const float var  = s2 * inv_n - mean * mean;
    const float a = gamma[c] * rsqrtf(var + EPSV);
    g_ab[c]          = a;
    g_ab[F_OUTC + c] = beta[c] - mean * a;
}

// ============================================================
// Kernel 4: BN + ELU
// ============================================================
__global__ void k_bn_elu(float* __restrict__ out) {
    __shared__ float sa[F_OUTC], sb[F_OUTC];
    if (threadIdx.x < F_OUTC) {
        sa[threadIdx.x] = g_ab[threadIdx.x];
        sb[threadIdx.x] = g_ab[F_OUTC + threadIdx.x];
    }
    __syncthreads();
    const int idx = blockIdx.x * blockDim.x + threadIdx.x;
    const int c = idx & (F_OUTC - 1);
    float v = g_vals[idx] * sa[c] + sb[c];
    out[idx] = v > 0.f ? v : expm1f(v);
}

// ============================================================
// launch
// ============================================================
extern "C" void kernel_launch(void* const* d_in, const int* in_sizes, int n_in,
                              void* d_out, int out_size) {
    const float* seq      = (const float*)d_in[0];
    const float* bias_mat = (const float*)d_in[1];
    const float* W1       = (const float*)d_in[2];
    const float* w2       = (const float*)d_in[3];
    const float* b2       = (const float*)d_in[4];
    const float* w3       = (const float*)d_in[5];
    const float* b3       = (const float*)d_in[6];
    const float* gamma    = (const float*)d_in[7];
    const float* beta     = (const float*)d_in[8];
    float* out = (float*)d_out;

    k_proj<<<B_SZ * N_NODES / 16, 256>>>(seq, W1, w2, b2, w3, b3);
    k_f2max<<<B_SZ, 256>>>();
    k_attn<<<dim3(NBLK, B_SZ), 128>>>(bias_mat);
    k_stats<<<1, F_OUTC>>>(gamma, beta);
    k_bn_elu<<<(B_SZ * N_NODES * F_OUTC) / 256, 256>>>(out);
}

// round 4
// speedup vs baseline: 2.5636x; 1.6764x over previous
#include <cuda_runtime.h>
#include <cuda_fp16.h>
#include <math.h>
#include <stdint.h>

// ---------------- problem constants ----------------
#define B_SZ    2
#define N_NODES 4096
#define F_INC   256
#define F_OUTC  64
#define TI      64               // i-rows per attention CTA
#define TJ      128              // j-chunk
#define NCHUNK  (N_NODES / TJ)   // 32
#define NBLK    (N_NODES / TI)   // 64 per batch
#define TOT_BLK (B_SZ * NBLK)    // 128
#define EPSV    1e-5f
#define SLOPE   0.01f
#define L2E     1.44269504088896340736f

// smem layout (dynamic)
#define SM_V0    0
#define SM_V1    16384
#define SM_B0    32768
#define SM_B1    (32768 + 33792)
#define SM_F0    100352
#define SM_F1    100864
#define SM_BN1   101376
#define SM_BN2   102400
#define SMEM_DYN 103424
#define BROWF    132            // floats per padded bias row (528 B, 16B aligned)

// ---------------- device scratch ----------------
__device__ __half g_fts_h[B_SZ * N_NODES * F_OUTC];
__device__ float  g_f1[B_SZ * N_NODES];
__device__ float  g_f2[B_SZ * N_NODES];
__device__ float  g_f2max[B_SZ];
__device__ float  g_vals[B_SZ * N_NODES * F_OUTC];
__device__ float  g_p1[TOT_BLK * F_OUTC];
__device__ float  g_p2[TOT_BLK * F_OUTC];
__device__ float  g_ab[2 * F_OUTC];

// ---------------- helpers (baseline PTX, sm_80+) ----------------
__device__ __forceinline__ void mma16816(float* c, const uint32_t* a, const uint32_t* b) {
    asm volatile("mma.sync.aligned.m16n8k16.row.col.f32.f16.f16.f32 "
        "{%0,%1,%2,%3}, {%4,%5,%6,%7}, {%8,%9}, {%0,%1,%2,%3};"
        : "+f"(c[0]), "+f"(c[1]), "+f"(c[2]), "+f"(c[3])
        : "r"(a[0]), "r"(a[1]), "r"(a[2]), "r"(a[3]), "r"(b[0]), "r"(b[1]));
}
__device__ __forceinline__ void ldsm4t(uint32_t* r, uint32_t addr) {
    asm volatile("ldmatrix.sync.aligned.m8n8.x4.trans.shared.b16 {%0,%1,%2,%3}, [%4];"
        : "=r"(r[0]), "=r"(r[1]), "=r"(r[2]), "=r"(r[3]) : "r"(addr));
}
__device__ __forceinline__ uint32_t smem_u32(const void* p) {
    return (uint32_t)__cvta_generic_to_shared(p);
}
__device__ __forceinline__ void cp16(uint32_t dst, const void* src) {
    asm volatile("cp.async.cg.shared.global [%0], [%1], 16;" :: "r"(dst), "l"(src));
}
__device__ __forceinline__ uint32_t ex2_h2(uint32_t yin) {
    uint32_t r;
    asm("ex2.approx.f16x2 %0, %1;" : "=r"(r) : "r"(yin));
    return r;
}
__device__ __forceinline__ float lrelu(float x) {
    return x > 0.f ? x : SLOPE * x;
}

// ============================================================
// Kernel 1: projection + f1/f2 + fp16 fts
// ============================================================
__global__ void k_proj(const float* __restrict__ seq,
                       const float* __restrict__ W1,
                       const float* __restrict__ w2,
                       const float* __restrict__ b2,
                       const float* __restrict__ w3,
                       const float* __restrict__ b3) {
    __shared__ __align__(16) float s_seq[16][F_INC];
    __shared__ float s_fts[16][F_OUTC + 4];

    const int t = threadIdx.x;
    const int rg0 = blockIdx.x * 16;

    {
        const float4* src = (const float4*)(seq + (size_t)rg0 * F_INC);
        float4* dst = (float4*)&s_seq[0][0];
        #pragma unroll
        for (int i = 0; i < (16 * F_INC / 4) / 256; i++)
            dst[t + i * 256] = src[t + i * 256];
    }
    __syncthreads();

    const int r  = t >> 4;
    const int c0 = (t & 15) * 4;
    float a0 = 0.f, a1 = 0.f, a2 = 0.f, a3 = 0.f;
    const float* wp = W1 + (size_t)c0 * F_INC;
    #pragma unroll 4
    for (int k = 0; k < F_INC; k += 4) {
        float4 sv  = *(const float4*)&s_seq[r][k];
        float4 w0v = __ldg((const float4*)(wp + k));
        float4 w1v = __ldg((const float4*)(wp + F_INC + k));
        float4 w2v = __ldg((const float4*)(wp + 2 * F_INC + k));
        float4 w3v = __ldg((const float4*)(wp + 3 * F_INC + k));
        a0 += sv.x * w0v.x + sv.y * w0v.y + sv.z * w0v.z + sv.w * w0v.w;
        a1 += sv.x * w1v.x + sv.y * w1v.y + sv.z * w1v.z + sv.w * w1v.w;
        a2 += sv.x * w2v.x + sv.y * w2v.y + sv.z * w2v.z + sv.w * w2v.w;
        a3 += sv.x * w3v.x + sv.y * w3v.y + sv.z * w3v.z + sv.w * w3v.w;
    }
    s_fts[r][c0 + 0] = a0;
    s_fts[r][c0 + 1] = a1;
    s_fts[r][c0 + 2] = a2;
    s_fts[r][c0 + 3] = a3;
    {
        __half2 h01 = __floats2half2_rn(a0, a1);
        __half2 h23 = __floats2half2_rn(a2, a3);
        uint2 u;
        u.x = *reinterpret_cast<uint32_t*>(&h01);
        u.y = *reinterpret_cast<uint32_t*>(&h23);
        *(uint2*)(g_fts_h + ((size_t)(rg0 + r)) * F_OUTC + c0) = u;
    }
    __syncthreads();

    if (t < 32) {
        int row = t >> 1;
        int sel = t & 1;
        const float* wv = sel ? w3 : w2;
        float acc = sel ? b3[0] : b2[0];
        #pragma unroll 8
        for (int c = 0; c < F_OUTC; c++) acc += s_fts[row][c] * wv[c];
        if (sel) g_f2[rg0 + row] = acc;
        else     g_f1[rg0 + row] = acc;
    }
}

// ============================================================
// Kernel 1b: per-batch max of f2
// ============================================================
__global__ void k_f2max() {
    __shared__ float red[256];
    const int b = blockIdx.x, t = threadIdx.x;
    float m = -1e30f;
    for (int i = t; i < N_NODES; i += 256)
        m = fmaxf(m, g_f2[b * N_NODES + i]);
    red[t] = m;
    __syncthreads();
    for (int o = 128; o; o >>= 1) {
        if (t < o) red[t] = fmaxf(red[t], red[t + o]);
        __syncthreads();
    }
    if (t == 0) g_f2max[b] = red[0];
}

// ============================================================
// Kernel 2: HMMA attention w/ cp.async double-buffered staging.
// grid (64, 2) x 128 threads (4 warps). Warp w: rows [w*16, w*16+16).
// ============================================================
__global__ __launch_bounds__(128)
void k_attn(const float* __restrict__ bias) {
    extern __shared__ __align__(128) char smem[];
    const uint32_t sb0 = smem_u32(smem);
    float* s_bn1 = (float*)(smem + SM_BN1);
    float* s_bn2 = (float*)(smem + SM_BN2);

    const int t    = threadIdx.x;
    const int warp = t >> 5;
    const int lane = t & 31;
    const int g    = lane >> 2;
    const int t4   = lane & 3;
    const int b    = blockIdx.y;
    const int i0   = blockIdx.x * TI;

    const int ra = warp * 16 + g;       // local rows ra, ra+8
    const float f1a = g_f1[b * N_NODES + i0 + ra];
    const float f1b = g_f1[b * N_NODES + i0 + ra + 8];
    const float f2m = g_f2max[b];
    const float mhaL = lrelu(f1a + f2m) * L2E;
    const float mhbL = lrelu(f1b + f2m) * L2E;

    const float* biasb = bias + ((size_t)(b * N_NODES + i0)) * N_NODES;

    float c[8][4];
    #pragma unroll
    for (int nt = 0; nt < 8; nt++)
        #pragma unroll
        for (int k = 0; k < 4; k++) c[nt][k] = 0.f;
    float lsum_a = 0.f, lsum_b = 0.f;

    // ---- staging: one chunk (V tile, bias tile, f2 chunk) into buffer s ----
    auto issue_chunk = [&](int ck, int s) {
        const int j0 = ck * TJ;
        const uint4* vsrc = (const uint4*)(g_fts_h + ((size_t)b * N_NODES + j0) * F_OUTC);
        const uint32_t vb = sb0 + (s ? SM_V1 : SM_V0);
        #pragma unroll
        for (int i = 0; i < 8; ++i) {
            uint32_t idx = (uint32_t)(t + 128 * i);
            uint32_t off = idx * 16u;
            cp16(vb + (off ^ ((off >> 3) & 0x70)), vsrc + idx);
        }
        const uint32_t bb = sb0 + (s ? SM_B1 : SM_B0);
        #pragma unroll
        for (int i = 0; i < 16; ++i) {
            uint32_t idx = (uint32_t)(t + 128 * i);
            uint32_t row = idx >> 5, seg = idx & 31;
            cp16(bb + row * (BROWF * 4) + seg * 16,
                 biasb + (size_t)row * N_NODES + j0 + seg * 4);
        }
        if (t < 32)
            cp16(sb0 + (s ? SM_F1 : SM_F0) + t * 16, g_f2 + b * N_NODES + j0 + t * 4);
        asm volatile("cp.async.commit_group;" ::: "memory");
    };

    issue_chunk(0, 0);
    issue_chunk(1, 1);

    for (int chk = 0; chk < NCHUNK; ++chk) {
        const int s = chk & 1;
        asm volatile("cp.async.wait_group 1;" ::: "memory");
        __syncthreads();

        const float* sf2 = (const float*)(smem + (s ? SM_F1 : SM_F0));
        const float* sba = (const float*)(smem + (s ? SM_B1 : SM_B0)) + ra * BROWF;
        const float* sbb = sba + 8 * BROWF;
        const uint32_t sv = sb0 + (s ? SM_V1 : SM_V0);

        #pragma unroll 2
        for (int kk = 0; kk < 8; ++kk) {
            const int jb = kk * 16 + 2 * t4;

            float2 f20 = *(const float2*)(sf2 + jb);
            float2 f21 = *(const float2*)(sf2 + jb + 8);
            float2 ba0 = *(const float2*)(sba + jb);
            float2 ba1 = *(const float2*)(sba + jb + 8);
            float2 bb0 = *(const float2*)(sbb + jb);
            float2 bb1 = *(const float2*)(sbb + jb + 8);

            // y = score*log2e - mh*log2e, exp via ex2.f16x2
            float ya0 = fmaf(lrelu(f1a + f20.x) + ba0.x, L2E, -mhaL);
            float ya1 = fmaf(lrelu(f1a + f20.y) + ba0.y, L2E, -mhaL);
            float ya2 = fmaf(lrelu(f1a + f21.x) + ba1.x, L2E, -mhaL);
            float ya3 = fmaf(lrelu(f1a + f21.y) + ba1.y, L2E, -mhaL);
            float yb0 = fmaf(lrelu(f1b + f20.x) + bb0.x, L2E, -mhbL);
            float yb1 = fmaf(lrelu(f1b + f20.y) + bb0.y, L2E, -mhbL);
            float yb2 = fmaf(lrelu(f1b + f21.x) + bb1.x, L2E, -mhbL);
            float yb3 = fmaf(lrelu(f1b + f21.y) + bb1.y, L2E, -mhbL);

            __half2 ta0 = __floats2half2_rn(ya0, ya1);
            __half2 ta1 = __floats2half2_rn(ya2, ya3);
            __half2 tb0 = __floats2half2_rn(yb0, yb1);
            __half2 tb1 = __floats2half2_rn(yb2, yb3);

            uint32_t a[4];
            a[0] = ex2_h2(*reinterpret_cast<uint32_t*>(&ta0));
            a[1] = ex2_h2(*reinterpret_cast<uint32_t*>(&tb0));
            a[2] = ex2_h2(*reinterpret_cast<uint32_t*>(&ta1));
            a[3] = ex2_h2(*reinterpret_cast<uint32_t*>(&tb1));

            // row sums from the rounded halves (consistent with MMA inputs)
            {
                float2 p;
                p = __half22float2(*(__half2*)&a[0]); lsum_a += p.x + p.y;
                p = __half22float2(*(__half2*)&a[2]); lsum_a += p.x + p.y;
                p = __half22float2(*(__half2*)&a[1]); lsum_b += p.x + p.y;
                p = __half22float2(*(__half2*)&a[3]); lsum_b += p.x + p.y;
            }

            const uint32_t krow = (uint32_t)(kk * 16 + (lane & 15));
            #pragma unroll
            for (int nt2 = 0; nt2 < 4; ++nt2) {
                const uint32_t ncol = (uint32_t)((lane >> 4) * 8 + nt2 * 16);
                uint32_t off = krow * 128u + ncol * 2u;
                uint32_t addr = sv + (off ^ ((off >> 3) & 0x70));
                uint32_t bfr[4];
                ldsm4t(bfr, addr);
                mma16816(c[nt2 * 2 + 0], a, bfr + 0);
                mma16816(c[nt2 * 2 + 1], a, bfr + 2);
            }
        }
        __syncthreads();
        if (chk + 2 < NCHUNK) issue_chunk(chk + 2, s);
        else asm volatile("cp.async.commit_group;" ::: "memory");
    }

    // ---- finalize row sums ----
    lsum_a += __shfl_xor_sync(0xffffffffu, lsum_a, 1);
    lsum_a += __shfl_xor_sync(0xffffffffu, lsum_a, 2);
    lsum_b += __shfl_xor_sync(0xffffffffu, lsum_b, 1);
    lsum_b += __shfl_xor_sync(0xffffffffu, lsum_b, 2);
    const float inv_a = 1.f / lsum_a;
    const float inv_b = 1.f / lsum_b;

    // ---- scale, write vals, BN partials ----
    float* go_a = g_vals + ((size_t)b * N_NODES + i0 + ra) * F_OUTC;
    float* go_b = go_a + 8 * F_OUTC;

    #pragma unroll
    for (int nt = 0; nt < 8; ++nt) {
        float2 va, vb;
        va.x = c[nt][0] * inv_a; va.y = c[nt][1] * inv_a;
        vb.x = c[nt][2] * inv_b; vb.y = c[nt][3] * inv_b;
        *(float2*)(go_a + nt * 8 + 2 * t4) = va;
        *(float2*)(go_b + nt * 8 + 2 * t4) = vb;

        float sx = va.x + vb.x, sy = va.y + vb.y;
        float qx = va.x * va.x + vb.x * vb.x;
        float qy = va.y * va.y + vb.y * vb.y;
        #pragma unroll
        for (int o = 4; o < 32; o <<= 1) {
            sx += __shfl_xor_sync(0xffffffffu, sx, o);
            sy += __shfl_xor_sync(0xffffffffu, sy, o);
            qx += __shfl_xor_sync(0xffffffffu, qx, o);
            qy += __shfl_xor_sync(0xffffffffu, qy, o);
        }
        if (g == 0) {
            s_bn1[warp * F_OUTC + nt * 8 + 2 * t4 + 0] = sx;
            s_bn1[warp * F_OUTC + nt * 8 + 2 * t4 + 1] = sy;
            s_bn2[warp * F_OUTC + nt * 8 + 2 * t4 + 0] = qx;
            s_bn2[warp * F_OUTC + nt * 8 + 2 * t4 + 1] = qy;
        }
    }
    __syncthreads();

    if (t < F_OUTC) {
        float s1 = 0.f, s2 = 0.f;
        #pragma unroll
        for (int w = 0; w < 4; ++w) {
            s1 += s_bn1[w * F_OUTC + t];
            s2 += s_bn2[w * F_OUTC + t];
        }
        const int bid = b * NBLK + blockIdx.x;
        g_p1[bid * F_OUTC + t] = s1;
        g_p2[bid * F_OUTC + t] = s2;
    }
}

// ============================================================
// Kernel 3: BN stats (parallelized: 512 threads = 64 ch x 8 parts)
// ============================================================
__global__ void k_stats(const float* __restrict__ gamma,
                        const float* __restrict__ beta) {
    __shared__ float r1[512], r2[512];
    const int t = threadIdx.x;
    const int c = t & 63, p = t >> 6;
    float s1 = 0.f, s2 = 0.f;
    for (int i = p; i < TOT_BLK; i += 8) {
        s1 += g_p1[i * F_OUTC + c];
        s2 += g_p2[i * F_OUTC + c];
    }
    r1[t] = s1; r2[t] = s2;
    __syncthreads();
    if (p == 0) {
        #pragma unroll
        for (int q = 1; q < 8; q++) {
            s1 += r1[q * 64 + c];
            s2 += r2[q * 64 + c];
        }
        const float inv_n = 1.f / (float)(B_SZ * N_NODES);
        const float mean = s1 * inv_n;
        const float var  = s2 * inv_n - mean * mean;
        const float a = gamma[c] * rsqrtf(var + EPSV);
        g_ab[c]          = a;
        g_ab[F_OUTC + c] = beta[c] - mean * a;
    }
}

// ============================================================
// Kernel 4: BN + ELU (float4 vectorized)
// ============================================================
__global__ void k_bn_elu(float* __restrict__ out) {
    __shared__ float sa[F_OUTC], sb[F_OUTC];
    if (threadIdx.x < F_OUTC) {
        sa[threadIdx.x] = g_ab[threadIdx.x];
        sb[threadIdx.x] = g_ab[F_OUTC + threadIdx.x];
    }
    __syncthreads();
    const int idx = blockIdx.x * blockDim.x + threadIdx.x;
    const int c0 = (idx & 15) * 4;
    float4 v = *(const float4*)(g_vals + (size_t)idx * 4);
    float4 r;
    float x;
    x = v.x * sa[c0 + 0] + sb[c0 + 0]; r.x = x > 0.f ? x : expm1f(x);
    x = v.y * sa[c0 + 1] + sb[c0 + 1]; r.y = x > 0.f ? x : expm1f(x);
    x = v.z * sa[c0 + 2] + sb[c0 + 2]; r.z = x > 0.f ? x : expm1f(x);
    x = v.w * sa[c0 + 3] + sb[c0 + 3]; r.w = x > 0.f ? x : expm1f(x);
    *(float4*)(out + (size_t)idx * 4) = r;
}

// ============================================================
// launch
// ============================================================
extern "C" void kernel_launch(void* const* d_in, const int* in_sizes, int n_in,
                              void* d_out, int out_size) {
    const float* seq      = (const float*)d_in[0];
    const float* bias_mat = (const float*)d_in[1];
    const float* W1       = (const float*)d_in[2];
    const float* w2       = (const float*)d_in[3];
    const float* b2       = (const float*)d_in[4];
    const float* w3       = (const float*)d_in[5];
    const float* b3       = (const float*)d_in[6];
    const float* gamma    = (const float*)d_in[7];
    const float* beta     = (const float*)d_in[8];
    float* out = (float*)d_out;

    cudaFuncSetAttribute(k_attn, cudaFuncAttributeMaxDynamicSharedMemorySize, SMEM_DYN);

    k_proj<<<B_SZ * N_NODES / 16, 256>>>(seq, W1, w2, b2, w3, b3);
    k_f2max<<<B_SZ, 256>>>();
    k_attn<<<dim3(NBLK, B_SZ), 128, SMEM_DYN>>>(bias_mat);
    k_stats<<<1, 512>>>(gamma, beta);
    k_bn_elu<<<(B_SZ * N_NODES * F_OUTC) / 1024, 256>>>(out);
}

// round 5
// speedup vs baseline: 2.7049x; 1.0551x over previous
#include <cuda_runtime.h>
#include <cuda_fp16.h>
#include <math.h>
#include <stdint.h>

// ---------------- problem constants ----------------
#define B_SZ    2
#define N_NODES 4096
#define F_INC   256
#define F_OUTC  64
#define TI      64               // i-rows per attention CTA
#define TJ      64               // j-chunk per group step
#define NGRP    4                // j-groups per CTA (4 warps each)
#define JSPAN   (N_NODES / NGRP) // 1024 j per group
#define NCHK_G  (JSPAN / TJ)     // 16 chunks per group
#define NBLK    (N_NODES / TI)   // 64 per batch
#define TOT_BLK (B_SZ * NBLK)    // 128
#define EPSV    1e-5f
#define SLOPE   0.01f
#define L2E     1.44269504088896340736f

// per-group smem region layout (bytes)
#define BROWF   68               // padded floats per bias row (272B)
#define GB_V0   0
#define GB_V1   8192
#define GB_B0   16384
#define GB_B1   (16384 + 17408)
#define GB_F0   51200
#define GB_F1   51456
#define GBUF    51712            // per-group region size (128B multiple)
#define SMEM_DYN (NGRP * GBUF)   // 206848

// epilogue smem reuse (floats offsets)
#define EP_CSTRIDE 66            // padded col stride
#define EP_CAREA   (64 * EP_CSTRIDE)         // per-group C partial
#define EP_LS      (NGRP * EP_CAREA)         // [NGRP][64] lsums

// ---------------- device scratch ----------------
__device__ __half g_fts_h[B_SZ * N_NODES * F_OUTC];
__device__ float  g_f1[B_SZ * N_NODES];
__device__ float  g_f2[B_SZ * N_NODES];
__device__ float  g_f2max[B_SZ];
__device__ float  g_vals[B_SZ * N_NODES * F_OUTC];
__device__ float  g_p1[TOT_BLK * F_OUTC];
__device__ float  g_p2[TOT_BLK * F_OUTC];
__device__ float  g_ab[2 * F_OUTC];

// ---------------- helpers (baseline PTX, sm_80+) ----------------
__device__ __forceinline__ void mma16816(float* c, const uint32_t* a, const uint32_t* b) {
    asm volatile("mma.sync.aligned.m16n8k16.row.col.f32.f16.f16.f32 "
        "{%0,%1,%2,%3}, {%4,%5,%6,%7}, {%8,%9}, {%0,%1,%2,%3};"
        : "+f"(c[0]), "+f"(c[1]), "+f"(c[2]), "+f"(c[3])
        : "r"(a[0]), "r"(a[1]), "r"(a[2]), "r"(a[3]), "r"(b[0]), "r"(b[1]));
}
__device__ __forceinline__ void ldsm4t(uint32_t* r, uint32_t addr) {
    asm volatile("ldmatrix.sync.aligned.m8n8.x4.trans.shared.b16 {%0,%1,%2,%3}, [%4];"
        : "=r"(r[0]), "=r"(r[1]), "=r"(r[2]), "=r"(r[3]) : "r"(addr));
}
__device__ __forceinline__ uint32_t smem_u32(const void* p) {
    return (uint32_t)__cvta_generic_to_shared(p);
}
__device__ __forceinline__ void cp16(uint32_t dst, const void* src) {
    asm volatile("cp.async.cg.shared.global [%0], [%1], 16;" :: "r"(dst), "l"(src));
}
__device__ __forceinline__ uint32_t ex2_h2(uint32_t yin) {
    uint32_t r;
    asm("ex2.approx.f16x2 %0, %1;" : "=r"(r) : "r"(yin));
    return r;
}
__device__ __forceinline__ float lrelu(float x) {
    return x > 0.f ? x : SLOPE * x;
}
__device__ __forceinline__ void grp_bar(int id) {
    asm volatile("bar.sync %0, 128;" :: "r"(id) : "memory");
}

// ============================================================
// Kernel 1: projection + f1/f2 + fp16 fts
// ============================================================
__global__ void k_proj(const float* __restrict__ seq,
                       const float* __restrict__ W1,
                       const float* __restrict__ w2,
                       const float* __restrict__ b2,
                       const float* __restrict__ w3,
                       const float* __restrict__ b3) {
    __shared__ __align__(16) float s_seq[16][F_INC];
    __shared__ float s_fts[16][F_OUTC + 4];

    const int t = threadIdx.x;
    const int rg0 = blockIdx.x * 16;

    {
        const float4* src = (const float4*)(seq + (size_t)rg0 * F_INC);
        float4* dst = (float4*)&s_seq[0][0];
        #pragma unroll
        for (int i = 0; i < (16 * F_INC / 4) / 256; i++)
            dst[t + i * 256] = src[t + i * 256];
    }
    __syncthreads();

    const int r  = t >> 4;
    const int c0 = (t & 15) * 4;
    float a0 = 0.f, a1 = 0.f, a2 = 0.f, a3 = 0.f;
    const float* wp = W1 + (size_t)c0 * F_INC;
    #pragma unroll 4
    for (int k = 0; k < F_INC; k += 4) {
        float4 sv  = *(const float4*)&s_seq[r][k];
        float4 w0v = __ldg((const float4*)(wp + k));
        float4 w1v = __ldg((const float4*)(wp + F_INC + k));
        float4 w2v = __ldg((const float4*)(wp + 2 * F_INC + k));
        float4 w3v = __ldg((const float4*)(wp + 3 * F_INC + k));
        a0 += sv.x * w0v.x + sv.y * w0v.y + sv.z * w0v.z + sv.w * w0v.w;
        a1 += sv.x * w1v.x + sv.y * w1v.y + sv.z * w1v.z + sv.w * w1v.w;
        a2 += sv.x * w2v.x + sv.y * w2v.y + sv.z * w2v.z + sv.w * w2v.w;
        a3 += sv.x * w3v.x + sv.y * w3v.y + sv.z * w3v.z + sv.w * w3v.w;
    }
    s_fts[r][c0 + 0] = a0;
    s_fts[r][c0 + 1] = a1;
    s_fts[r][c0 + 2] = a2;
    s_fts[r][c0 + 3] = a3;
    {
        __half2 h01 = __floats2half2_rn(a0, a1);
        __half2 h23 = __floats2half2_rn(a2, a3);
        uint2 u;
        u.x = *reinterpret_cast<uint32_t*>(&h01);
        u.y = *reinterpret_cast<uint32_t*>(&h23);
        *(uint2*)(g_fts_h + ((size_t)(rg0 + r)) * F_OUTC + c0) = u;
    }
    __syncthreads();

    if (t < 32) {
        int row = t >> 1;
        int sel = t & 1;
        const float* wv = sel ? w3 : w2;
        float acc = sel ? b3[0] : b2[0];
        #pragma unroll 8
        for (int c = 0; c < F_OUTC; c++) acc += s_fts[row][c] * wv[c];
        if (sel) g_f2[rg0 + row] = acc;
        else     g_f1[rg0 + row] = acc;
    }
}

// ============================================================
// Kernel 1b: per-batch max of f2
// ============================================================
__global__ void k_f2max() {
    __shared__ float red[256];
    const int b = blockIdx.x, t = threadIdx.x;
    float m = -1e30f;
    for (int i = t; i < N_NODES; i += 256)
        m = fmaxf(m, g_f2[b * N_NODES + i]);
    red[t] = m;
    __syncthreads();
    for (int o = 128; o; o >>= 1) {
        if (t < o) red[t] = fmaxf(red[t], red[t + o]);
        __syncthreads();
    }
    if (t == 0) g_f2max[b] = red[0];
}

// ============================================================
// Kernel 2: HMMA attention, 512 threads = 4 independent j-groups
// of 4 warps. Each group: private cp.async double-buffered pipe
// over its 1024-wide j-span. grid (64, 2).
// ============================================================
__global__ __launch_bounds__(512, 1)
void k_attn(const float* __restrict__ bias) {
    extern __shared__ __align__(128) char smem[];
    const uint32_t sb0 = smem_u32(smem);

    const int t    = threadIdx.x;
    const int gp   = t >> 7;          // j-group 0..3
    const int gt   = t & 127;         // thread within group
    const int warp = gt >> 5;         // row-group 0..3
    const int lane = t & 31;
    const int g    = lane >> 2;
    const int t4   = lane & 3;
    const int b    = blockIdx.y;
    const int i0   = blockIdx.x * TI;

    char*          gbp = smem + gp * GBUF;
    const uint32_t gb  = sb0 + gp * GBUF;

    const int ra = warp * 16 + g;     // local rows ra, ra+8
    const float f1a = g_f1[b * N_NODES + i0 + ra];
    const float f1b = g_f1[b * N_NODES + i0 + ra + 8];
    const float f2m = g_f2max[b];
    const float mhaL = lrelu(f1a + f2m) * L2E;
    const float mhbL = lrelu(f1b + f2m) * L2E;

    const float* biasb = bias + ((size_t)(b * N_NODES + i0)) * N_NODES + gp * JSPAN;
    const int    jg0   = b * N_NODES + gp * JSPAN;   // base into g_f2 / g_fts_h

    float c[8][4];
    #pragma unroll
    for (int nt = 0; nt < 8; nt++)
        #pragma unroll
        for (int k = 0; k < 4; k++) c[nt][k] = 0.f;
    float lsum_a = 0.f, lsum_b = 0.f;

    // ---- stage one chunk (V, bias, f2) into buffer s of this group ----
    auto issue_chunk = [&](int ck, int s) {
        const int j0 = ck * TJ;
        const uint4* vsrc = (const uint4*)(g_fts_h + ((size_t)jg0 + j0) * F_OUTC);
        const uint32_t vb = gb + (s ? GB_V1 : GB_V0);
        #pragma unroll
        for (int i = 0; i < 4; ++i) {
            uint32_t idx = (uint32_t)(gt + 128 * i);
            uint32_t off = idx * 16u;
            cp16(vb + (off ^ ((off >> 3) & 0x70)), vsrc + idx);
        }
        const uint32_t bb = gb + (s ? GB_B1 : GB_B0);
        #pragma unroll
        for (int i = 0; i < 8; ++i) {
            uint32_t idx = (uint32_t)(gt + 128 * i);
            uint32_t row = idx >> 4, seg = idx & 15;
            cp16(bb + row * (BROWF * 4) + seg * 16,
                 biasb + (size_t)row * N_NODES + j0 + seg * 4);
        }
        if (gt < 16)
            cp16(gb + (s ? GB_F1 : GB_F0) + gt * 16, g_f2 + jg0 + j0 + gt * 4);
        asm volatile("cp.async.commit_group;" ::: "memory");
    };

    issue_chunk(0, 0);
    issue_chunk(1, 1);

    for (int chk = 0; chk < NCHK_G; ++chk) {
        const int s = chk & 1;
        asm volatile("cp.async.wait_group 1;" ::: "memory");
        grp_bar(gp + 1);

        const float* sf2 = (const float*)(gbp + (s ? GB_F1 : GB_F0));
        const float* sba = (const float*)(gbp + (s ? GB_B1 : GB_B0)) + ra * BROWF;
        const float* sbb = sba + 8 * BROWF;
        const uint32_t sv = gb + (s ? GB_V1 : GB_V0);

        #pragma unroll
        for (int kk = 0; kk < 4; ++kk) {
            const int jb = kk * 16 + 2 * t4;

            float2 f20 = *(const float2*)(sf2 + jb);
            float2 f21 = *(const float2*)(sf2 + jb + 8);
            float2 ba0 = *(const float2*)(sba + jb);
            float2 ba1 = *(const float2*)(sba + jb + 8);
            float2 bb0 = *(const float2*)(sbb + jb);
            float2 bb1 = *(const float2*)(sbb + jb + 8);

            float ya0 = fmaf(lrelu(f1a + f20.x) + ba0.x, L2E, -mhaL);
            float ya1 = fmaf(lrelu(f1a + f20.y) + ba0.y, L2E, -mhaL);
            float ya2 = fmaf(lrelu(f1a + f21.x) + ba1.x, L2E, -mhaL);
            float ya3 = fmaf(lrelu(f1a + f21.y) + ba1.y, L2E, -mhaL);
            float yb0 = fmaf(lrelu(f1b + f20.x) + bb0.x, L2E, -mhbL);
            float yb1 = fmaf(lrelu(f1b + f20.y) + bb0.y, L2E, -mhbL);
            float yb2 = fmaf(lrelu(f1b + f21.x) + bb1.x, L2E, -mhbL);
            float yb3 = fmaf(lrelu(f1b + f21.y) + bb1.y, L2E, -mhbL);

            __half2 ta0 = __floats2half2_rn(ya0, ya1);
            __half2 ta1 = __floats2half2_rn(ya2, ya3);
            __half2 tb0 = __floats2half2_rn(yb0, yb1);
            __half2 tb1 = __floats2half2_rn(yb2, yb3);

            uint32_t a[4];
            a[0] = ex2_h2(*reinterpret_cast<uint32_t*>(&ta0));
            a[1] = ex2_h2(*reinterpret_cast<uint32_t*>(&tb0));
            a[2] = ex2_h2(*reinterpret_cast<uint32_t*>(&ta1));
            a[3] = ex2_h2(*reinterpret_cast<uint32_t*>(&tb1));

            {
                float2 p;
                p = __half22float2(*(__half2*)&a[0]); lsum_a += p.x + p.y;
                p = __half22float2(*(__half2*)&a[2]); lsum_a += p.x + p.y;
                p = __half22float2(*(__half2*)&a[1]); lsum_b += p.x + p.y;
                p = __half22float2(*(__half2*)&a[3]); lsum_b += p.x + p.y;
            }

            const uint32_t krow = (uint32_t)(kk * 16 + (lane & 15));
            #pragma unroll
            for (int nt2 = 0; nt2 < 4; ++nt2) {
                const uint32_t ncol = (uint32_t)((lane >> 4) * 8 + nt2 * 16);
                uint32_t off = krow * 128u + ncol * 2u;
                uint32_t addr = sv + (off ^ ((off >> 3) & 0x70));
                uint32_t bfr[4];
                ldsm4t(bfr, addr);
                mma16816(c[nt2 * 2 + 0], a, bfr + 0);
                mma16816(c[nt2 * 2 + 1], a, bfr + 2);
            }
        }
        grp_bar(gp + 1);
        if (chk + 2 < NCHK_G) issue_chunk(chk + 2, s);
        else asm volatile("cp.async.commit_group;" ::: "memory");
    }
    asm volatile("cp.async.wait_all;" ::: "memory");

    // ---- finalize per-warp partial row sums ----
    lsum_a += __shfl_xor_sync(0xffffffffu, lsum_a, 1);
    lsum_a += __shfl_xor_sync(0xffffffffu, lsum_a, 2);
    lsum_b += __shfl_xor_sync(0xffffffffu, lsum_b, 1);
    lsum_b += __shfl_xor_sync(0xffffffffu, lsum_b, 2);

    __syncthreads();   // all groups done; smem reusable

    // ---- dump partial C and lsums ----
    float* sf = (float*)smem;
    float* carea = sf + gp * EP_CAREA;
    #pragma unroll
    for (int nt = 0; nt < 8; ++nt) {
        const int col = nt * 8 + 2 * t4;
        *(float2*)(carea + ra * EP_CSTRIDE + col)       = make_float2(c[nt][0], c[nt][1]);
        *(float2*)(carea + (ra + 8) * EP_CSTRIDE + col) = make_float2(c[nt][2], c[nt][3]);
    }
    if (t4 == 0) {
        sf[EP_LS + gp * 64 + ra]     = lsum_a;
        sf[EP_LS + gp * 64 + ra + 8] = lsum_b;
    }
    __syncthreads();

    // ---- combine groups: thread t -> row t>>3, cols (t&7)*8 .. +7 ----
    {
        const int row = t >> 3;
        const int c0  = (t & 7) * 8;
        const float inv = 1.f / (sf[EP_LS + row] + sf[EP_LS + 64 + row] +
                                 sf[EP_LS + 128 + row] + sf[EP_LS + 192 + row]);
        float v[8];
        #pragma unroll
        for (int e = 0; e < 8; ++e) {
            const int o = row * EP_CSTRIDE + c0 + e;
            v[e] = (sf[o] + sf[EP_CAREA + o] + sf[2 * EP_CAREA + o] + sf[3 * EP_CAREA + o]) * inv;
        }
        float* go = g_vals + ((size_t)b * N_NODES + i0 + row) * F_OUTC + c0;
        *(float4*)(go)     = make_float4(v[0], v[1], v[2], v[3]);
        *(float4*)(go + 4) = make_float4(v[4], v[5], v[6], v[7]);
        #pragma unroll
        for (int e = 0; e < 8; ++e)
            sf[row * EP_CSTRIDE + c0 + e] = v[e];   // own slot; combined vals for BN
    }
    __syncthreads();

    // ---- deterministic BN partials ----
    if (t < F_OUTC) {
        float s1 = 0.f, s2 = 0.f;
        #pragma unroll 8
        for (int r = 0; r < TI; ++r) {
            float v = sf[r * EP_CSTRIDE + t];
            s1 += v;
            s2 += v * v;
        }
        const int bid = b * NBLK + blockIdx.x;
        g_p1[bid * F_OUTC + t] = s1;
        g_p2[bid * F_OUTC + t] = s2;
    }
}

// ============================================================
// Kernel 3: BN stats — one block per channel
// ============================================================
__global__ void k_stats(const float* __restrict__ gamma,
                        const float* __restrict__ beta) {
    __shared__ float r1[128], r2[128];
    const int c = blockIdx.x, t = threadIdx.x;
    r1[t] = g_p1[t * F_OUTC + c];
    r2[t] = g_p2[t * F_OUTC + c];
    __syncthreads();
    for (int o = 64; o; o >>= 1) {
        if (t < o) { r1[t] += r1[t + o]; r2[t] += r2[t + o]; }
        __syncthreads();
    }
    if (t == 0) {
        const float inv_n = 1.f / (float)(B_SZ * N_NODES);
        const float mean = r1[0] * inv_n;
        const float var  = r2[0] * inv_n - mean * mean;
        const float a = gamma[c] * rsqrtf(var + EPSV);
        g_ab[c]          = a;
        g_ab[F_OUTC + c] = beta[c] - mean * a;
    }
}

// ============================================================
// Kernel 4: BN + ELU (float4 vectorized)
// ============================================================
__global__ void k_bn_elu(float* __restrict__ out) {
    __shared__ float sa[F_OUTC], sb[F_OUTC];
    if (threadIdx.x < F_OUTC) {
        sa[threadIdx.x] = g_ab[threadIdx.x];
        sb[threadIdx.x] = g_ab[F_OUTC + threadIdx.x];
    }
    __syncthreads();
    const int idx = blockIdx.x * blockDim.x + threadIdx.x;
    const int c0 = (idx & 15) * 4;
    float4 v = *(const float4*)(g_vals + (size_t)idx * 4);
    float4 r;
    float x;
    x = v.x * sa[c0 + 0] + sb[c0 + 0]; r.x = x > 0.f ? x : expm1f(x);
    x = v.y * sa[c0 + 1] + sb[c0 + 1]; r.y = x > 0.f ? x : expm1f(x);
    x = v.z * sa[c0 + 2] + sb[c0 + 2]; r.z = x > 0.f ? x : expm1f(x);
    x = v.w * sa[c0 + 3] + sb[c0 + 3]; r.w = x > 0.f ? x : expm1f(x);
    *(float4*)(out + (size_t)idx * 4) = r;
}

// ============================================================
// launch
// ============================================================
extern "C" void kernel_launch(void* const* d_in, const int* in_sizes, int n_in,
                              void* d_out, int out_size) {
    const float* seq      = (const float*)d_in[0];
    const float* bias_mat = (const float*)d_in[1];
    const float* W1       = (const float*)d_in[2];
    const float* w2       = (const float*)d_in[3];
    const float* b2       = (const float*)d_in[4];
    const float* w3       = (const float*)d_in[5];
    const float* b3       = (const float*)d_in[6];
    const float* gamma    = (const float*)d_in[7];
    const float* beta     = (const float*)d_in[8];
    float* out = (float*)d_out;

    cudaFuncSetAttribute(k_attn, cudaFuncAttributeMaxDynamicSharedMemorySize, SMEM_DYN);

    k_proj<<<B_SZ * N_NODES / 16, 256>>>(seq, W1, w2, b2, w3, b3);
    k_f2max<<<B_SZ, 256>>>();
    k_attn<<<dim3(NBLK, B_SZ), 512, SMEM_DYN>>>(bias_mat);
    k_stats<<<F_OUTC, 128>>>(gamma, beta);
    k_bn_elu<<<(B_SZ * N_NODES * F_OUTC) / 1024, 256>>>(out);
}